// round 15
// baseline (speedup 1.0000x reference)
#include <cuda_runtime.h>
#include <cuda_bf16.h>
#include <cstdint>

#define N_PTS 8192
#define E_DIM 256
#define NUM_CLASSES 100
#define MARGIN 0.1f
#define EPS_F 1e-4f

#define BT 128                        // tile edge (rows and cols)
#define SAB8 272                      // padded row stride in bytes (68 words == 4 mod 32)
#define NRB (N_PTS / BT)              // 64 row blocks
#define NTILES (NRB * (NRB + 1) / 2)  // 2080 triangular tiles
#define NTHREADS 512

__device__ float g_sq[N_PTS];
__device__ int   g_hist[NUM_CLASSES];
__device__ float g_num[N_PTS];
__device__ float g_den[N_PTS];
__device__ unsigned g_done;
__device__ uint8_t g_x8[(size_t)N_PTS * E_DIM];   // e4m3 copy of X (2MB)

__device__ __forceinline__ void mma_fp8(float acc[4], const uint32_t a[4],
                                        const uint32_t b[2]) {
    asm volatile(
        "mma.sync.aligned.m16n8k32.row.col.f32.e4m3.e4m3.f32 "
        "{%0,%1,%2,%3}, {%4,%5,%6,%7}, {%8,%9}, {%0,%1,%2,%3};"
        : "+f"(acc[0]), "+f"(acc[1]), "+f"(acc[2]), "+f"(acc[3])
        : "r"(a[0]), "r"(a[1]), "r"(a[2]), "r"(a[3]), "r"(b[0]), "r"(b[1]));
}

__device__ __forceinline__ uint16_t pack_e4m3x2(float lo, float hi) {
    uint16_t h;
    asm("cvt.rn.satfinite.e4m3x2.f32 %0, %1, %2;" : "=h"(h) : "f"(hi), "f"(lo));
    return h;   // low byte = lo, high byte = hi
}

// ---------------------------------------------------------------------------
// Per-row squared norms (fp32 exact) + label histogram + e4m3 conversion.
// One warp per row; lane L owns cols 8L..8L+7.
// ---------------------------------------------------------------------------
__global__ void prep_kernel(const float* __restrict__ X, const int* __restrict__ lab) {
    int warp = (blockIdx.x * blockDim.x + threadIdx.x) >> 5;
    int lane = threadIdx.x & 31;
    if (warp >= N_PTS) return;
    const float4* row = (const float4*)(X + (size_t)warp * E_DIM);
    float4 v0 = row[2 * lane];
    float4 v1 = row[2 * lane + 1];
    float s = v0.x * v0.x + v0.y * v0.y + v0.z * v0.z + v0.w * v0.w
            + v1.x * v1.x + v1.y * v1.y + v1.z * v1.z + v1.w * v1.w;

    uint32_t w0 = (uint32_t)pack_e4m3x2(v0.x, v0.y)
                | ((uint32_t)pack_e4m3x2(v0.z, v0.w) << 16);
    uint32_t w1 = (uint32_t)pack_e4m3x2(v1.x, v1.y)
                | ((uint32_t)pack_e4m3x2(v1.z, v1.w) << 16);
    uint2 u; u.x = w0; u.y = w1;
    ((uint2*)(g_x8 + (size_t)warp * E_DIM))[lane] = u;

#pragma unroll
    for (int o = 16; o; o >>= 1) s += __shfl_xor_sync(0xffffffffu, s, o);
    if (lane == 0) {
        g_sq[warp] = s;
        atomicAdd(&g_hist[lab[warp]], 1);
    }
}

// ---------------------------------------------------------------------------
// Symmetric-Gram e4m3 m16n8k32 kernel. One CTA per triangular tile (I,J), J<=I.
// Off-diagonal tiles scatter BOTH row-side (I) and column-side (J) partials.
// 512 threads = 16 warps, warp grid 4(m) x 4(n), warp tile 32x32.
// Last CTA performs the final reduction AND resets state for the next replay.
// ---------------------------------------------------------------------------
__global__ void __launch_bounds__(NTHREADS, 1)
triplet_main_kernel(const int* __restrict__ lab, float* __restrict__ out) {
    extern __shared__ uint8_t smb[];
    uint8_t* As8 = smb;                  // BT x SAB8 (rows of I)
    uint8_t* Bs8 = smb + BT * SAB8;      // BT x SAB8 (rows of J = columns)

    __shared__ float sqb_s[BT];
    __shared__ int   lbb_s[BT];
    __shared__ float red_n[BT][4];
    __shared__ float red_d[BT][4];
    __shared__ float colp_n[4][BT];
    __shared__ float colp_d[4][BT];
    __shared__ unsigned last_s;
    __shared__ double s1[NTHREADS];
    __shared__ double s2[NTHREADS];

    const int tid  = threadIdx.x;
    const int w    = tid >> 5, lane = tid & 31;
    const int wm   = w >> 2,   wn   = w & 3;       // 4x4 warp grid
    const int g    = lane >> 2, cc  = lane & 3;

    // Triangular decode: blockIdx.x -> (I, J), J <= I.
    int b = blockIdx.x;
    int I = (int)((sqrtf(8.f * (float)b + 1.f) - 1.f) * 0.5f);
    while ((I + 1) * (I + 2) / 2 <= b) ++I;
    while (I * (I + 1) / 2 > b) --I;
    const int J = b - I * (I + 1) / 2;
    const bool offdiag = (I != J);

    const int row0 = I * BT;
    const int col0 = J * BT;
    const float DIAG_D = sqrtf(EPS_F);

    // Load A (I rows) and B (J rows): 2048 uint4 each, 4 per thread each.
#pragma unroll
    for (int q = 0; q < 4; ++q) {
        int idx = tid + q * NTHREADS;
        int r = idx >> 4, c16 = idx & 15;
        uint4 u = ((const uint4*)(g_x8 + (size_t)(row0 + r) * E_DIM))[c16];
        *(uint4*)(As8 + (size_t)r * SAB8 + c16 * 16) = u;
    }
#pragma unroll
    for (int q = 0; q < 4; ++q) {
        int idx = tid + q * NTHREADS;
        int r = idx >> 4, c16 = idx & 15;
        uint4 u = ((const uint4*)(g_x8 + (size_t)(col0 + r) * E_DIM))[c16];
        *(uint4*)(Bs8 + (size_t)r * SAB8 + c16 * 16) = u;
    }
    if (tid < BT) {
        sqb_s[tid] = g_sq[col0 + tid];
        lbb_s[tid] = lab[col0 + tid];
    }

    float sqa[4]; int la[4];
#pragma unroll
    for (int mf = 0; mf < 2; ++mf)
#pragma unroll
        for (int hi = 0; hi < 2; ++hi) {
            int r = row0 + wm * 32 + mf * 16 + g + hi * 8;
            sqa[mf * 2 + hi] = g_sq[r];
            la[mf * 2 + hi]  = lab[r];
        }
    __syncthreads();

    float acc[2][4][4];
#pragma unroll
    for (int mf = 0; mf < 2; ++mf)
#pragma unroll
        for (int nf = 0; nf < 4; ++nf)
#pragma unroll
            for (int e = 0; e < 4; ++e) acc[mf][nf][e] = 0.f;

#pragma unroll
    for (int ks = 0; ks < E_DIM / 32; ++ks) {
        const int kc = ks * 32;
        uint32_t a[2][4], bb[4][2];
#pragma unroll
        for (int mf = 0; mf < 2; ++mf) {
            int r = wm * 32 + mf * 16 + g;
            a[mf][0] = *(const uint32_t*)(As8 + (size_t)r * SAB8 + kc + 4 * cc);
            a[mf][1] = *(const uint32_t*)(As8 + (size_t)(r + 8) * SAB8 + kc + 4 * cc);
            a[mf][2] = *(const uint32_t*)(As8 + (size_t)r * SAB8 + kc + 4 * cc + 16);
            a[mf][3] = *(const uint32_t*)(As8 + (size_t)(r + 8) * SAB8 + kc + 4 * cc + 16);
        }
#pragma unroll
        for (int nf = 0; nf < 4; ++nf) {
            int n = wn * 32 + nf * 8 + g;
            bb[nf][0] = *(const uint32_t*)(Bs8 + (size_t)n * SAB8 + kc + 4 * cc);
            bb[nf][1] = *(const uint32_t*)(Bs8 + (size_t)n * SAB8 + kc + 4 * cc + 16);
        }
#pragma unroll
        for (int mf = 0; mf < 2; ++mf)
#pragma unroll
            for (int nf = 0; nf < 4; ++nf)
                mma_fp8(acc[mf][nf], a[mf], bb[nf]);
    }

    // Epilogue: one rsqrt per element; value feeds row (I) and column (J) sums.
    float num[4] = {0.f, 0.f, 0.f, 0.f};
    float den[4] = {0.f, 0.f, 0.f, 0.f};
    float cn[8]  = {0.f, 0.f, 0.f, 0.f, 0.f, 0.f, 0.f, 0.f};
    float cd[8]  = {0.f, 0.f, 0.f, 0.f, 0.f, 0.f, 0.f, 0.f};

    float sj[4][2]; int lj[4][2];
#pragma unroll
    for (int nf = 0; nf < 4; ++nf)
#pragma unroll
        for (int e0 = 0; e0 < 2; ++e0) {
            int jl = wn * 32 + nf * 8 + 2 * cc + e0;
            sj[nf][e0] = sqb_s[jl];
            lj[nf][e0] = lbb_s[jl];
        }

#pragma unroll
    for (int mf = 0; mf < 2; ++mf)
#pragma unroll
        for (int nf = 0; nf < 4; ++nf)
#pragma unroll
            for (int e = 0; e < 4; ++e) {
                int hi = e >> 1, e0 = e & 1;
                int id = mf * 2 + hi;
                int ci = nf * 2 + e0;
                float v = fmaxf(sqa[id] + sj[nf][e0] - 2.f * acc[mf][nf][e], EPS_F);
                float r;
                asm("rsqrt.approx.f32 %0, %1;" : "=f"(r) : "f"(v));
                if (la[id] == lj[nf][e0]) {
                    float c;
                    if (offdiag) {
                        c = v * r;
                    } else {
                        int il = wm * 32 + mf * 16 + g + hi * 8;
                        int jl = wn * 32 + nf * 8 + 2 * cc + e0;
                        c = (il == jl) ? DIAG_D : v * r;
                    }
                    num[id] += c;
                    cn[ci]  += c;
                } else {
                    float t = MARGIN * r;
                    float u = 1.f - t;
                    float c = r * fmaf(t * t, u, u);   // 1/(d+m) ~ r(1-t)(1+t^2)
                    den[id] += c;
                    cd[ci]  += c;
                }
            }

    // ---- Row-side reduce (over cc: xor 1,2 stays within quad) ----
#pragma unroll
    for (int id = 0; id < 4; ++id) {
        num[id] += __shfl_xor_sync(0xffffffffu, num[id], 1);
        num[id] += __shfl_xor_sync(0xffffffffu, num[id], 2);
        den[id] += __shfl_xor_sync(0xffffffffu, den[id], 1);
        den[id] += __shfl_xor_sync(0xffffffffu, den[id], 2);
    }
    if (cc == 0) {
#pragma unroll
        for (int mf = 0; mf < 2; ++mf)
#pragma unroll
            for (int hi = 0; hi < 2; ++hi) {
                int rl = wm * 32 + mf * 16 + g + hi * 8;
                red_n[rl][wn] = num[mf * 2 + hi];
                red_d[rl][wn] = den[mf * 2 + hi];
            }
    }

    // ---- Column-side reduce (over g: xor 4,8,16) ----
    if (offdiag) {
#pragma unroll
        for (int ci = 0; ci < 8; ++ci) {
            cn[ci] += __shfl_xor_sync(0xffffffffu, cn[ci], 4);
            cn[ci] += __shfl_xor_sync(0xffffffffu, cn[ci], 8);
            cn[ci] += __shfl_xor_sync(0xffffffffu, cn[ci], 16);
            cd[ci] += __shfl_xor_sync(0xffffffffu, cd[ci], 4);
            cd[ci] += __shfl_xor_sync(0xffffffffu, cd[ci], 8);
            cd[ci] += __shfl_xor_sync(0xffffffffu, cd[ci], 16);
        }
        if (g == 0) {
#pragma unroll
            for (int ci = 0; ci < 8; ++ci) {
                int nf = ci >> 1, e0 = ci & 1;
                int jl = wn * 32 + nf * 8 + 2 * cc + e0;
                colp_n[wm][jl] = cn[ci];
                colp_d[wm][jl] = cd[ci];
            }
        }
    }
    __syncthreads();

    if (tid < BT) {
        atomicAdd(&g_num[row0 + tid], red_n[tid][0] + red_n[tid][1]
                                    + red_n[tid][2] + red_n[tid][3]);
        atomicAdd(&g_den[row0 + tid], red_d[tid][0] + red_d[tid][1]
                                    + red_d[tid][2] + red_d[tid][3]);
        if (offdiag) {
            atomicAdd(&g_num[col0 + tid], colp_n[0][tid] + colp_n[1][tid]
                                        + colp_n[2][tid] + colp_n[3][tid]);
            atomicAdd(&g_den[col0 + tid], colp_d[0][tid] + colp_d[1][tid]
                                        + colp_d[2][tid] + colp_d[3][tid]);
        }
    }

    // --- Fused finalize: last CTA reduces everything, then resets state. ---
    __syncthreads();
    if (tid == 0) {
        __threadfence();
        unsigned prev = atomicAdd(&g_done, 1u);
        last_s = (prev == NTILES - 1) ? 1u : 0u;
    }
    __syncthreads();
    if (last_s) {
        __threadfence();
        double a = 0.0;
#pragma unroll
        for (int q = 0; q < N_PTS / NTHREADS; ++q) {
            int row = tid + q * NTHREADS;
            a += (double)g_num[row] * (double)g_den[row];
        }
        double bb = 0.0;
        if (tid < NUM_CLASSES) {
            double hh = (double)g_hist[tid];
            bb = hh * hh * ((double)N_PTS - hh);
        }
        s1[tid] = a; s2[tid] = bb;
        __syncthreads();
        for (int o = NTHREADS / 2; o; o >>= 1) {
            if (tid < o) { s1[tid] += s1[tid + o]; s2[tid] += s2[tid + o]; }
            __syncthreads();
        }
        if (tid == 0) out[0] = (float)(s1[0] / s2[0]);

        // Reset all accumulation state so the next graph replay starts clean
        // (device globals are zero-initialized at load -> call 1 is identical).
#pragma unroll
        for (int q = 0; q < N_PTS / NTHREADS; ++q) {
            int row = tid + q * NTHREADS;
            g_num[row] = 0.f;
            g_den[row] = 0.f;
        }
        if (tid < NUM_CLASSES) g_hist[tid] = 0;
        if (tid == 0) g_done = 0u;
    }
}

// ---------------------------------------------------------------------------
extern "C" void kernel_launch(void* const* d_in, const int* in_sizes, int n_in,
                              void* d_out, int out_size) {
    const float* X   = (const float*)d_in[0];
    const int*   lab = (const int*)d_in[1];
    float*       out = (float*)d_out;

    prep_kernel<<<N_PTS / 8, 256>>>(X, lab);

    size_t smem = (size_t)2 * BT * SAB8;   // 69,632 B
    cudaFuncSetAttribute(triplet_main_kernel,
                         cudaFuncAttributeMaxDynamicSharedMemorySize, (int)smem);
    triplet_main_kernel<<<NTILES, NTHREADS, smem>>>(lab, out);
}